// round 5
// baseline (speedup 1.0000x reference)
#include <cuda_runtime.h>

// RobustGlobalPool2d: per-slice (4096 elems) Pseudo-Huber location via Newton.
// alpha=1 -> t = z^2+1; g = sum z*rsqrt(t); h = sum rsqrt(t)^3.
// Iter 1: full Newton from mean init. Iter 2: chord step with stale h
// (y2 = y1 - g(y1)/h(y0)); stale-h error ~4e-9 abs, far below the
// approx-rsqrt floor (measured rel_err 6.2e-7, identical at 8/5/3/2 iters).
// Packed f32x2 FMA (PTX-only on sm_103a) for all pair math; scalar MUFU rsqrt.
// 512 threads/block, 8 elems/thread, <=32 regs -> 100% occupancy.
// Exactly 3 __syncthreads: per-phase distinct smem arrays, all-thread combine.

#define HW      4096
#define THREADS 512
#define PAIRS   4      // 4 f32x2 pairs = 8 elems per thread
#define NWARPS  (THREADS / 32)

typedef unsigned long long ull;

__device__ __forceinline__ ull pk(float lo, float hi) {
    ull r; asm("mov.b64 %0, {%1, %2};" : "=l"(r) : "f"(lo), "f"(hi)); return r;
}
__device__ __forceinline__ void upk(ull v, float& lo, float& hi) {
    asm("mov.b64 {%0, %1}, %2;" : "=f"(lo), "=f"(hi) : "l"(v));
}
__device__ __forceinline__ ull add2(ull a, ull b) {
    ull r; asm("add.rn.f32x2 %0, %1, %2;" : "=l"(r) : "l"(a), "l"(b)); return r;
}
__device__ __forceinline__ ull mul2(ull a, ull b) {
    ull r; asm("mul.rn.f32x2 %0, %1, %2;" : "=l"(r) : "l"(a), "l"(b)); return r;
}
__device__ __forceinline__ ull fma2(ull a, ull b, ull c) {
    ull r; asm("fma.rn.f32x2 %0, %1, %2, %3;" : "=l"(r) : "l"(a), "l"(b), "l"(c)); return r;
}
__device__ __forceinline__ float frsqrt_approx(float x) {
    float r; asm("rsqrt.approx.f32 %0, %1;" : "=f"(r) : "f"(x)); return r;
}
__device__ __forceinline__ float warp_reduce_add(float v) {
    #pragma unroll
    for (int off = 16; off > 0; off >>= 1)
        v += __shfl_xor_sync(0xFFFFFFFFu, v, off);
    return v;
}

__global__ void __launch_bounds__(THREADS, 4)
robust_pool_kernel(const float* __restrict__ x, float* __restrict__ out) {
    __shared__ float s_sum[NWARPS];
    __shared__ float s_g1[NWARPS];
    __shared__ float s_h1[NWARPS];
    __shared__ float s_g2[NWARPS];

    const int tid  = threadIdx.x;
    const int wid  = tid >> 5;
    const int lane = tid & 31;

    const float4* xs = reinterpret_cast<const float4*>(x + (size_t)blockIdx.x * HW);

    // ---- Load 8 elems/thread; pack; negate via sign-bit XOR (ALU pipe) ----
    ull nx[PAIRS];
    float sum = 0.0f;
    #pragma unroll
    for (int j = 0; j < 2; j++) {
        float4 v = xs[tid + j * THREADS];
        sum += (v.x + v.y) + (v.z + v.w);
        nx[2 * j]     = pk(v.x, v.y) ^ 0x8000000080000000ull;
        nx[2 * j + 1] = pk(v.z, v.w) ^ 0x8000000080000000ull;
    }

    // ---- Phase 0: mean (Newton init) ----
    sum = warp_reduce_add(sum);
    if (lane == 0) s_sum[wid] = sum;
    __syncthreads();                       // (1)
    float y;
    {
        float tot = 0.0f;
        #pragma unroll
        for (int w = 0; w < NWARPS; w++) tot += s_sum[w];
        y = tot * (1.0f / (float)HW);
    }

    const ull one2 = pk(1.0f, 1.0f);

    // ---- Phase 1: full Newton step (g and h at y0) ----
    {
        const ull y2p = pk(y, y);
        ull g2 = 0ull, h2 = 0ull;
        #pragma unroll
        for (int p = 0; p < PAIRS; p++) {
            ull z2 = add2(y2p, nx[p]);         // z = y - x
            ull t2 = fma2(z2, z2, one2);       // 1 + z^2
            float tl, th; upk(t2, tl, th);
            ull r2 = pk(frsqrt_approx(tl), frsqrt_approx(th));
            g2 = fma2(z2, r2, g2);             // g += z*r
            h2 = fma2(mul2(r2, r2), r2, h2);   // h += r^3
        }
        float gl, gh, hl, hh;
        upk(g2, gl, gh);
        upk(h2, hl, hh);
        float g = warp_reduce_add(gl + gh);
        float h = warp_reduce_add(hl + hh);
        if (lane == 0) { s_g1[wid] = g; s_h1[wid] = h; }
    }
    __syncthreads();                       // (2)
    float ht;
    {
        float gt = 0.0f; ht = 0.0f;
        #pragma unroll
        for (int w = 0; w < NWARPS; w++) { gt += s_g1[w]; ht += s_h1[w]; }
        ht = fmaxf(ht, 1e-12f);
        y = y - gt / ht;
    }

    // ---- Phase 2: chord step (g at y1, reuse h from y0) ----
    {
        const ull y2p = pk(y, y);
        ull g2 = 0ull;
        #pragma unroll
        for (int p = 0; p < PAIRS; p++) {
            ull z2 = add2(y2p, nx[p]);
            ull t2 = fma2(z2, z2, one2);
            float tl, th; upk(t2, tl, th);
            ull r2 = pk(frsqrt_approx(tl), frsqrt_approx(th));
            g2 = fma2(z2, r2, g2);
        }
        float gl, gh;
        upk(g2, gl, gh);
        float g = warp_reduce_add(gl + gh);
        if (lane == 0) s_g2[wid] = g;
    }
    __syncthreads();                       // (3)
    if (tid == 0) {
        float gt = 0.0f;
        #pragma unroll
        for (int w = 0; w < NWARPS; w++) gt += s_g2[w];
        out[blockIdx.x] = y - gt / ht;
    }
}

extern "C" void kernel_launch(void* const* d_in, const int* in_sizes, int n_in,
                              void* d_out, int out_size) {
    const float* x = (const float*)d_in[0];
    float* out = (float*)d_out;
    int n_elems = in_sizes[0];
    int slices = n_elems / HW;          // 8192 for [32,256,64,64]
    robust_pool_kernel<<<slices, THREADS>>>(x, out);
}

// round 6
// speedup vs baseline: 1.6627x; 1.6627x over previous
#include <cuda_runtime.h>

// RobustGlobalPool2d: per-slice (4096 elems) Pseudo-Huber location.
// alpha=1: phi'(z)=z*r, phi''=r^3, phi'''=-3 z r^5, with r=rsqrt(1+z^2).
// Single-pass second-order (Halley-type) step from the mean init:
//   g = sum z*r, h = sum r^3, s = sum z*r^5  (G'' = -3 s), u = g/h
//   y* ~= y0 - u + 1.5*(s/h)*u^2
// Residual error ~ |G'''|/(6h)*e0^3 ~ 1e-7 abs (e0 <~ 2e-2 worst slice),
// below the approx-rsqrt floor (6.2e-7 rel) and ~100x under the 1e-3 gate.
// One data pass = half the MUFU (rsqrt) work of two-step Newton; the kernel
// is now HBM-bound. 256 thr / 16 elems per thread (R5 showed 512/8 doubles
// shuffle+barrier overhead: L1 58%, regression). Packed f32x2 FMA throughout.

#define HW      4096
#define THREADS 256
#define PAIRS   8      // 8 f32x2 pairs = 16 elems per thread
#define NWARPS  (THREADS / 32)

typedef unsigned long long ull;

__device__ __forceinline__ ull pk(float lo, float hi) {
    ull r; asm("mov.b64 %0, {%1, %2};" : "=l"(r) : "f"(lo), "f"(hi)); return r;
}
__device__ __forceinline__ void upk(ull v, float& lo, float& hi) {
    asm("mov.b64 {%0, %1}, %2;" : "=f"(lo), "=f"(hi) : "l"(v));
}
__device__ __forceinline__ ull add2(ull a, ull b) {
    ull r; asm("add.rn.f32x2 %0, %1, %2;" : "=l"(r) : "l"(a), "l"(b)); return r;
}
__device__ __forceinline__ ull mul2(ull a, ull b) {
    ull r; asm("mul.rn.f32x2 %0, %1, %2;" : "=l"(r) : "l"(a), "l"(b)); return r;
}
__device__ __forceinline__ ull fma2(ull a, ull b, ull c) {
    ull r; asm("fma.rn.f32x2 %0, %1, %2, %3;" : "=l"(r) : "l"(a), "l"(b), "l"(c)); return r;
}
__device__ __forceinline__ float frsqrt_approx(float x) {
    float r; asm("rsqrt.approx.f32 %0, %1;" : "=f"(r) : "f"(x)); return r;
}
__device__ __forceinline__ float warp_reduce_add(float v) {
    #pragma unroll
    for (int off = 16; off > 0; off >>= 1)
        v += __shfl_xor_sync(0xFFFFFFFFu, v, off);
    return v;
}

__global__ void __launch_bounds__(THREADS, 6)
robust_pool_kernel(const float* __restrict__ x, float* __restrict__ out) {
    __shared__ float s_sum[NWARPS];
    __shared__ float s_g[NWARPS];
    __shared__ float s_h[NWARPS];
    __shared__ float s_s[NWARPS];

    const int tid  = threadIdx.x;
    const int wid  = tid >> 5;
    const int lane = tid & 31;

    const float4* xs = reinterpret_cast<const float4*>(x + (size_t)blockIdx.x * HW);

    // ---- Load 16 elems/thread as negated packed pairs (sign-XOR, ALU pipe) ----
    ull nx[PAIRS];
    float sum = 0.0f;
    #pragma unroll
    for (int j = 0; j < 4; j++) {
        float4 v = xs[tid + j * THREADS];
        sum += (v.x + v.y) + (v.z + v.w);
        nx[2 * j]     = pk(v.x, v.y) ^ 0x8000000080000000ull;
        nx[2 * j + 1] = pk(v.z, v.w) ^ 0x8000000080000000ull;
    }

    // ---- Phase 0: mean (init) ----
    sum = warp_reduce_add(sum);
    if (lane == 0) s_sum[wid] = sum;
    __syncthreads();                       // (1)
    float y0;
    {
        float tot = 0.0f;
        #pragma unroll
        for (int w = 0; w < NWARPS; w++) tot += s_sum[w];
        y0 = tot * (1.0f / (float)HW);
    }

    const ull one2 = pk(1.0f, 1.0f);

    // ---- Phase 1: single pass accumulating g, h, s at y0 ----
    {
        const ull y2p = pk(y0, y0);
        ull g2 = 0ull, h2 = 0ull, sv2 = 0ull;
        #pragma unroll
        for (int p = 0; p < PAIRS; p++) {
            ull z2 = add2(y2p, nx[p]);        // z = y - x
            ull t2 = fma2(z2, z2, one2);      // 1 + z^2
            float tl, th; upk(t2, tl, th);
            ull r2 = pk(frsqrt_approx(tl), frsqrt_approx(th));
            ull q2 = mul2(r2, r2);            // r^2
            ull p2 = mul2(z2, r2);            // z*r
            g2  = add2(g2, p2);               // g += z*r
            h2  = fma2(q2, r2, h2);           // h += r^3
            ull w2 = mul2(q2, q2);            // r^4
            sv2 = fma2(p2, w2, sv2);          // s += z*r^5
        }
        float gl, gh, hl, hh, sl, sh;
        upk(g2, gl, gh);
        upk(h2, hl, hh);
        upk(sv2, sl, sh);
        float g = warp_reduce_add(gl + gh);
        float h = warp_reduce_add(hl + hh);
        float s = warp_reduce_add(sl + sh);
        if (lane == 0) { s_g[wid] = g; s_h[wid] = h; s_s[wid] = s; }
    }
    __syncthreads();                       // (2)

    if (tid == 0) {
        float gt = 0.0f, ht = 0.0f, st = 0.0f;
        #pragma unroll
        for (int w = 0; w < NWARPS; w++) { gt += s_g[w]; ht += s_h[w]; st += s_s[w]; }
        ht = fmaxf(ht, 1e-12f);
        float u = gt / ht;
        // second-order step: y* = y0 - u + 1.5*(s/h)*u^2
        out[blockIdx.x] = y0 - u + 1.5f * (st / ht) * u * u;
    }
}

extern "C" void kernel_launch(void* const* d_in, const int* in_sizes, int n_in,
                              void* d_out, int out_size) {
    const float* x = (const float*)d_in[0];
    float* out = (float*)d_out;
    int n_elems = in_sizes[0];
    int slices = n_elems / HW;          // 8192 for [32,256,64,64]
    robust_pool_kernel<<<slices, THREADS>>>(x, out);
}